// round 8
// baseline (speedup 1.0000x reference)
#include <cuda_runtime.h>

// HairBundle SDE drift + constant diffusion. Streaming, memory-bound.
// Floor: 480MB traffic -> ~60us @ 8TB/s. R5: warp-tiled smem transpose,
// 74.2us total (kernel 70.8us, DRAM 75%). R6: persistent warps, 4 tiles each,
// next-tile LDGs issued before current-tile compute (software pipeline) to
// hide DRAM latency behind ~400cyc of work per tile.

#define TPB 256
#define WPB (TPB / 32)
#define TILES_PER_WARP 4
#define F4T 160                      // float4 per warp-tile = 128 rows

__device__ __forceinline__ void hb_row(float x_hb, float x_a, float p_m,
                                       float p_gs, float p_t, float force,
                                       float* __restrict__ o) {
    float z    = 4.0f * (x_hb - x_a);                 // (x_hb - x_a)/DELTA
    float p_o  = 1.0f / (1.0f + __expf(-z));          // sigmoid
    float f_gs = 0.75f * (x_hb - x_a - 0.5f * p_o);
    o[0] = -f_gs - 0.6f * x_hb + force;
    o[1] = 0.1f * (f_gs - 0.45f * x_a - 0.35f * (1.0f - 0.9f * p_m));
    o[2] = 1.2f * p_o * (1.0f - p_m)  - 0.8f * p_m;
    o[3] = 0.7f * p_o * (1.0f - p_gs) - 0.5f * p_gs;
    o[4] = 0.3f * p_o * (1.0f - p_t)  - 0.4f * p_t;
}

__device__ __forceinline__ void diffu_stg(float4* __restrict__ dst, int lane) {
    // pattern period 5 over f4 index; tile base % 5 == 0; 32 % 5 == 2
    int m = lane % 5;
    #pragma unroll
    for (int k = 0; k < 5; k++) {
        int p = m + 2 * k; p %= 5;
        float4 v = (p == 0) ? make_float4(0.05f, 0.02f, 0.0f,  0.0f)  :
                   (p == 1) ? make_float4(0.0f,  0.05f, 0.02f, 0.0f)  :
                   (p == 2) ? make_float4(0.0f,  0.0f,  0.05f, 0.02f) :
                   (p == 3) ? make_float4(0.0f,  0.0f,  0.0f,  0.05f) :
                              make_float4(0.02f, 0.0f,  0.0f,  0.0f);
        __stcs(dst + lane + k * 32, v);
    }
}

__global__ __launch_bounds__(TPB, 5)
void hb_kernel(const float* __restrict__ t,
               const float4* __restrict__ x4,
               float4* __restrict__ drift4,
               float4* __restrict__ diffu4,
               const float* __restrict__ xs,
               float* __restrict__ drs,
               float* __restrict__ dfs,
               int ntiles, int nwarps, int B) {
    __shared__ float4 buf[WPB][F4T];
    const int lane = threadIdx.x & 31;
    const int w    = threadIdx.x >> 5;
    const int wid  = blockIdx.x * WPB + w;

    const float force = 0.5f * __sinf(6.283185307179586f * t[0]);

    const int tile0   = wid * TILES_PER_WARP;
    int nmine = ntiles - tile0;
    if (nmine > TILES_PER_WARP) nmine = TILES_PER_WARP;

    if (nmine > 0) {
        size_t base = (size_t)tile0 * F4T;
        // prologue: stage tile 0
        float4 s0 = x4[base + lane +   0];
        float4 s1 = x4[base + lane +  32];
        float4 s2 = x4[base + lane +  64];
        float4 s3 = x4[base + lane +  96];
        float4 s4 = x4[base + lane + 128];
        diffu_stg(diffu4 + base, lane);      // fills prologue LDG window
        buf[w][lane +   0] = s0;
        buf[w][lane +  32] = s1;
        buf[w][lane +  64] = s2;
        buf[w][lane +  96] = s3;
        buf[w][lane + 128] = s4;
        __syncwarp();

        for (int j = 0; ; ) {
            const bool more = (j + 1 < nmine);
            const size_t nbase = base + F4T;
            if (more) {                       // prefetch next tile NOW
                s0 = x4[nbase + lane +   0];
                s1 = x4[nbase + lane +  32];
                s2 = x4[nbase + lane +  64];
                s3 = x4[nbase + lane +  96];
                s4 = x4[nbase + lane + 128];
            }

            // compute 4 rows from smem, sliding window, write back in place
            {
                const int i5 = lane * 5;
                float4 a = buf[w][i5 + 0];
                float4 b = buf[w][i5 + 1];
                float o0[5], o1[5];
                hb_row(a.x, a.y, a.z, a.w, b.x, force, o0);   // row 0
                float4 c = buf[w][i5 + 2];
                hb_row(b.y, b.z, b.w, c.x, c.y, force, o1);   // row 1
                buf[w][i5 + 0] = make_float4(o0[0], o0[1], o0[2], o0[3]);
                buf[w][i5 + 1] = make_float4(o0[4], o1[0], o1[1], o1[2]);
                float4 d = buf[w][i5 + 3];
                float o2[5];
                hb_row(c.z, c.w, d.x, d.y, d.z, force, o2);   // row 2
                buf[w][i5 + 2] = make_float4(o1[3], o1[4], o2[0], o2[1]);
                float4 e = buf[w][i5 + 4];
                float o3[5];
                hb_row(d.w, e.x, e.y, e.z, e.w, force, o3);   // row 3
                buf[w][i5 + 3] = make_float4(o2[2], o2[3], o2[4], o3[0]);
                buf[w][i5 + 4] = make_float4(o3[1], o3[2], o3[3], o3[4]);
            }
            __syncwarp();

            // drift out (coalesced, streaming) + next tile's diffusion
            __stcs(drift4 + base + lane +   0, buf[w][lane +   0]);
            __stcs(drift4 + base + lane +  32, buf[w][lane +  32]);
            __stcs(drift4 + base + lane +  64, buf[w][lane +  64]);
            __stcs(drift4 + base + lane +  96, buf[w][lane +  96]);
            __stcs(drift4 + base + lane + 128, buf[w][lane + 128]);
            if (more) diffu_stg(diffu4 + nbase, lane);
            __syncwarp();                    // all lanes done reading buf

            if (!more) break;
            buf[w][lane +   0] = s0;         // stage prefetched tile
            buf[w][lane +  32] = s1;
            buf[w][lane +  64] = s2;
            buf[w][lane +  96] = s3;
            buf[w][lane + 128] = s4;
            __syncwarp();
            base = nbase;
            ++j;
        }
    }

    // scalar remainder rows [ntiles*128, B) — last warp only (empty for B=8M)
    if (wid == nwarps - 1) {
        for (int r = ntiles * 128 + lane; r < B; r += 32) {
            const float* xr = xs + (size_t)r * 5;
            float o[5];
            hb_row(xr[0], xr[1], xr[2], xr[3], xr[4], force, o);
            float* dr = drs + (size_t)r * 5;
            float* gr = dfs + (size_t)r * 5;
            dr[0] = o[0]; dr[1] = o[1]; dr[2] = o[2]; dr[3] = o[3]; dr[4] = o[4];
            gr[0] = 0.05f; gr[1] = 0.02f; gr[2] = 0.0f; gr[3] = 0.0f; gr[4] = 0.0f;
        }
    }
}

extern "C" void kernel_launch(void* const* d_in, const int* in_sizes, int n_in,
                              void* d_out, int out_size) {
    const float* t  = (const float*)d_in[0];   // [1]
    const float* x  = (const float*)d_in[1];   // [B*5]
    float* out      = (float*)d_out;
    int B           = in_sizes[1] / 5;
    int nf4         = in_sizes[1] / 4;         // B*5 % 4 == 0 for B=8M
    float* drift    = out;
    float* diffu    = out + (size_t)out_size / 2;

    int ntiles = nf4 / F4T;                    // 62500 for B=8M (exact)
    int nwarps = (ntiles + TILES_PER_WARP - 1) / TILES_PER_WARP;
    if (nwarps < 1) nwarps = 1;                // remainder-only safety
    int nblocks = (nwarps + WPB - 1) / WPB;    // 1954 for B=8M

    hb_kernel<<<nblocks, TPB>>>(t, (const float4*)x,
                                (float4*)drift, (float4*)diffu,
                                x, drift, diffu, ntiles, nwarps, B);
}

// round 9
// speedup vs baseline: 1.0718x; 1.0718x over previous
#include <cuda_runtime.h>
#include <cstdint>

// HairBundle SDE drift + constant diffusion. Streaming, memory-bound.
// Floor: 480MB traffic -> ~60us @ 8TB/s.
// R5 (best): warp-tiled smem transpose, LDG->STS staging, 74.2us, occ 62.8%.
// R6: multi-tile pipeline FAILED (occ 52%, 82us) - more warps beat per-warp hiding.
// R7: R5 structure + cp.async.cg staging (no data regs) + launch_bounds(256,8)
//     -> 64 warps/SM, loads absorbed by async queue instead of scoreboard.

#define TPB 256
#define WPB (TPB / 32)
#define F4T 160                      // float4 per warp-tile = 128 rows

__device__ __forceinline__ void hb_row(float x_hb, float x_a, float p_m,
                                       float p_gs, float p_t, float force,
                                       float* __restrict__ o) {
    float z    = 4.0f * (x_hb - x_a);                 // (x_hb - x_a)/DELTA
    float p_o  = 1.0f / (1.0f + __expf(-z));          // sigmoid
    float f_gs = 0.75f * (x_hb - x_a - 0.5f * p_o);
    o[0] = -f_gs - 0.6f * x_hb + force;
    o[1] = 0.1f * (f_gs - 0.45f * x_a - 0.35f * (1.0f - 0.9f * p_m));
    o[2] = 1.2f * p_o * (1.0f - p_m)  - 0.8f * p_m;
    o[3] = 0.7f * p_o * (1.0f - p_gs) - 0.5f * p_gs;
    o[4] = 0.3f * p_o * (1.0f - p_t)  - 0.4f * p_t;
}

__device__ __forceinline__ void cp_async16(uint32_t smem_addr, const void* gptr) {
    asm volatile("cp.async.cg.shared.global [%0], [%1], 16;\n"
                 :: "r"(smem_addr), "l"(gptr));
}

__global__ __launch_bounds__(TPB, 8)
void hb_kernel(const float* __restrict__ t,
               const float4* __restrict__ x4,
               float4* __restrict__ drift4,
               float4* __restrict__ diffu4,
               int nf4, int B) {
    __shared__ float4 buf[WPB][F4T];
    const int lane = threadIdx.x & 31;
    const int w    = threadIdx.x >> 5;
    const int wid  = blockIdx.x * WPB + w;            // global warp id
    const int base = wid * F4T;                        // f4 offset (fits int)
    if (base >= nf4) return;

    const float force = 0.5f * __sinf(6.283185307179586f * t[0]);

    if (base + F4T <= nf4) {
        // ============ full warp: cp.async staged, coalesced path ============
        uint32_t sbase = (uint32_t)__cvta_generic_to_shared(&buf[w][0]);
        #pragma unroll
        for (int k = 0; k < 5; k++)
            cp_async16(sbase + (uint32_t)(lane + k * 32) * 16u,
                       x4 + base + lane + k * 32);
        asm volatile("cp.async.commit_group;\n" ::: "memory");

        // diffusion stores: dependency-free, fill the async-load window.
        // base % 5 == 0 (160 % 5 == 0), 32 % 5 == 2 -> pattern = (lane%5 + 2k) % 5
        {
            int m = lane % 5;
            #pragma unroll
            for (int k = 0; k < 5; k++) {
                int p = m + 2 * k; p %= 5;
                float4 v = (p == 0) ? make_float4(0.05f, 0.02f, 0.0f,  0.0f)  :
                           (p == 1) ? make_float4(0.0f,  0.05f, 0.02f, 0.0f)  :
                           (p == 2) ? make_float4(0.0f,  0.0f,  0.05f, 0.02f) :
                           (p == 3) ? make_float4(0.0f,  0.0f,  0.0f,  0.05f) :
                                      make_float4(0.02f, 0.0f,  0.0f,  0.0f);
                __stcs(diffu4 + base + lane + k * 32, v);
            }
        }

        asm volatile("cp.async.wait_group 0;\n" ::: "memory");
        __syncwarp();

        // compute 4 rows from smem (stride-5 reads), write back in place
        {
            const int i5 = lane * 5;
            float4 a = buf[w][i5 + 0];
            float4 b = buf[w][i5 + 1];
            float o0[5], o1[5];
            hb_row(a.x, a.y, a.z, a.w, b.x, force, o0);       // row 0
            float4 c = buf[w][i5 + 2];
            hb_row(b.y, b.z, b.w, c.x, c.y, force, o1);       // row 1
            buf[w][i5 + 0] = make_float4(o0[0], o0[1], o0[2], o0[3]);
            buf[w][i5 + 1] = make_float4(o0[4], o1[0], o1[1], o1[2]);
            float4 d = buf[w][i5 + 3];
            float o2[5];
            hb_row(c.z, c.w, d.x, d.y, d.z, force, o2);       // row 2
            buf[w][i5 + 2] = make_float4(o1[3], o1[4], o2[0], o2[1]);
            float4 e = buf[w][i5 + 4];
            float o3[5];
            hb_row(d.w, e.x, e.y, e.z, e.w, force, o3);       // row 3
            buf[w][i5 + 3] = make_float4(o2[2], o2[3], o2[4], o3[0]);
            buf[w][i5 + 4] = make_float4(o3[1], o3[2], o3[3], o3[4]);
        }
        __syncwarp();

        // stream drift out: coalesced STG.128, write-streaming
        __stcs(drift4 + base + lane +   0, buf[w][lane +   0]);
        __stcs(drift4 + base + lane +  32, buf[w][lane +  32]);
        __stcs(drift4 + base + lane +  64, buf[w][lane +  64]);
        __stcs(drift4 + base + lane +  96, buf[w][lane +  96]);
        __stcs(drift4 + base + lane + 128, buf[w][lane + 128]);
    } else {
        // ============ partial warp: scalar per-row fallback ============
        const float* xs = (const float*)x4;
        float* drs = (float*)drift4;
        float* dfs = (float*)diffu4;
        int row0 = wid * 128;                 // 160 f4 = 128 rows per warp
        for (int r = row0 + lane; r < B; r += 32) {
            const float* xr = xs + (size_t)r * 5;
            float o[5];
            hb_row(xr[0], xr[1], xr[2], xr[3], xr[4], force, o);
            float* dr = drs + (size_t)r * 5;
            float* gr = dfs + (size_t)r * 5;
            dr[0] = o[0]; dr[1] = o[1]; dr[2] = o[2]; dr[3] = o[3]; dr[4] = o[4];
            gr[0] = 0.05f; gr[1] = 0.02f; gr[2] = 0.0f; gr[3] = 0.0f; gr[4] = 0.0f;
        }
    }
}

extern "C" void kernel_launch(void* const* d_in, const int* in_sizes, int n_in,
                              void* d_out, int out_size) {
    const float* t  = (const float*)d_in[0];   // [1]
    const float* x  = (const float*)d_in[1];   // [B*5]
    float* out      = (float*)d_out;
    int B           = in_sizes[1] / 5;
    int nf4         = in_sizes[1] / 4;         // B*5 % 4 == 0 for B=8M
    float* drift    = out;
    float* diffu    = out + (size_t)out_size / 2;

    int nwarps  = (nf4 + F4T - 1) / F4T;            // 62500 for B=8M
    int nblocks = (nwarps + WPB - 1) / WPB;         // 7813

    hb_kernel<<<nblocks, TPB>>>(t, (const float4*)x,
                                (float4*)drift, (float4*)diffu, nf4, B);
}

// round 10
// speedup vs baseline: 1.0877x; 1.0148x over previous
#include <cuda_runtime.h>
#include <cstdint>

// HairBundle SDE drift + constant diffusion. Streaming, memory-bound.
// Floor: 480MB traffic. R4/R5/R7 all pin at ~71us kernel (~5.9TB/s, 74-75%
// DRAM) across occ 63%..87% -> not latency-bound; suspected HBM r/w-mix
// scheduling wall. R8: 2-tile double-buffered cp.async pipeline per warp to
// keep the read stream continuously fed while writes drain.

#define TPB 256
#define WPB (TPB / 32)
#define F4T 160                      // float4 per warp-tile = 128 rows
#define ROWS_PER_WARP 256            // 2 tiles

__device__ __forceinline__ void hb_row(float x_hb, float x_a, float p_m,
                                       float p_gs, float p_t, float force,
                                       float* __restrict__ o) {
    float z    = 4.0f * (x_hb - x_a);                 // (x_hb - x_a)/DELTA
    float p_o  = 1.0f / (1.0f + __expf(-z));          // sigmoid
    float f_gs = 0.75f * (x_hb - x_a - 0.5f * p_o);
    o[0] = -f_gs - 0.6f * x_hb + force;
    o[1] = 0.1f * (f_gs - 0.45f * x_a - 0.35f * (1.0f - 0.9f * p_m));
    o[2] = 1.2f * p_o * (1.0f - p_m)  - 0.8f * p_m;
    o[3] = 0.7f * p_o * (1.0f - p_gs) - 0.5f * p_gs;
    o[4] = 0.3f * p_o * (1.0f - p_t)  - 0.4f * p_t;
}

__device__ __forceinline__ void cp_async16(uint32_t smem_addr, const void* gptr) {
    asm volatile("cp.async.cg.shared.global [%0], [%1], 16;\n"
                 :: "r"(smem_addr), "l"(gptr));
}

__device__ __forceinline__ void diffu_stg(float4* __restrict__ dst, int lane) {
    // period-5 f4 pattern; tile base % 5 == 0; 32 % 5 == 2
    int m = lane % 5;
    #pragma unroll
    for (int k = 0; k < 5; k++) {
        int p = m + 2 * k; p %= 5;
        float4 v = (p == 0) ? make_float4(0.05f, 0.02f, 0.0f,  0.0f)  :
                   (p == 1) ? make_float4(0.0f,  0.05f, 0.02f, 0.0f)  :
                   (p == 2) ? make_float4(0.0f,  0.0f,  0.05f, 0.02f) :
                   (p == 3) ? make_float4(0.0f,  0.0f,  0.0f,  0.05f) :
                              make_float4(0.02f, 0.0f,  0.0f,  0.0f);
        __stcs(dst + lane + k * 32, v);
    }
}

// compute 4 rows in place in a warp-private 160-f4 slab (lane slice i5=lane*5)
__device__ __forceinline__ void compute_tile(float4* __restrict__ sb, int lane,
                                             float force) {
    const int i5 = lane * 5;
    float4 a = sb[i5 + 0];
    float4 b = sb[i5 + 1];
    float o0[5], o1[5];
    hb_row(a.x, a.y, a.z, a.w, b.x, force, o0);       // row 0
    float4 c = sb[i5 + 2];
    hb_row(b.y, b.z, b.w, c.x, c.y, force, o1);       // row 1
    sb[i5 + 0] = make_float4(o0[0], o0[1], o0[2], o0[3]);
    sb[i5 + 1] = make_float4(o0[4], o1[0], o1[1], o1[2]);
    float4 d = sb[i5 + 3];
    float o2[5];
    hb_row(c.z, c.w, d.x, d.y, d.z, force, o2);       // row 2
    sb[i5 + 2] = make_float4(o1[3], o1[4], o2[0], o2[1]);
    float4 e = sb[i5 + 4];
    float o3[5];
    hb_row(d.w, e.x, e.y, e.z, e.w, force, o3);       // row 3
    sb[i5 + 3] = make_float4(o2[2], o2[3], o2[4], o3[0]);
    sb[i5 + 4] = make_float4(o3[1], o3[2], o3[3], o3[4]);
}

__device__ __forceinline__ void drift_stg(float4* __restrict__ dst,
                                          const float4* __restrict__ sb,
                                          int lane) {
    __stcs(dst + lane +   0, sb[lane +   0]);
    __stcs(dst + lane +  32, sb[lane +  32]);
    __stcs(dst + lane +  64, sb[lane +  64]);
    __stcs(dst + lane +  96, sb[lane +  96]);
    __stcs(dst + lane + 128, sb[lane + 128]);
}

__global__ __launch_bounds__(TPB, 5)
void hb_kernel(const float* __restrict__ t,
               const float4* __restrict__ x4,
               float4* __restrict__ drift4,
               float4* __restrict__ diffu4,
               int nf4, int B) {
    __shared__ float4 buf[WPB][2][F4T];   // 40KB/block
    const int lane = threadIdx.x & 31;
    const int w    = threadIdx.x >> 5;
    const int wid  = blockIdx.x * WPB + w;            // global warp id
    const int base = wid * (2 * F4T);                  // f4 offset, tile pair

    const float force = 0.5f * __sinf(6.283185307179586f * t[0]);

    const int row_base = wid * ROWS_PER_WARP;
    if (row_base >= B) return;
    int nfull = 0;                                     // full 128-row tiles mine
    if (row_base + 128 <= B) nfull = 1;
    if (row_base + 256 <= B) nfull = 2;

    if (nfull == 2) {
        // ---- issue reads for BOTH tiles up front (2 cp.async groups) ----
        uint32_t s0 = (uint32_t)__cvta_generic_to_shared(&buf[w][0][0]);
        uint32_t s1 = (uint32_t)__cvta_generic_to_shared(&buf[w][1][0]);
        #pragma unroll
        for (int k = 0; k < 5; k++)
            cp_async16(s0 + (uint32_t)(lane + k * 32) * 16u,
                       x4 + base + lane + k * 32);
        asm volatile("cp.async.commit_group;\n" ::: "memory");
        #pragma unroll
        for (int k = 0; k < 5; k++)
            cp_async16(s1 + (uint32_t)(lane + k * 32) * 16u,
                       x4 + base + F4T + lane + k * 32);
        asm volatile("cp.async.commit_group;\n" ::: "memory");

        // ---- both tiles' diffusion: fills the read window ----
        diffu_stg(diffu4 + base, lane);
        diffu_stg(diffu4 + base + F4T, lane);

        // ---- tile 0: wait (1 group may remain outstanding), compute, store
        asm volatile("cp.async.wait_group 1;\n" ::: "memory");
        __syncwarp();
        compute_tile(&buf[w][0][0], lane, force);
        __syncwarp();
        drift_stg(drift4 + base, &buf[w][0][0], lane);

        // ---- tile 1 ----
        asm volatile("cp.async.wait_group 0;\n" ::: "memory");
        __syncwarp();
        compute_tile(&buf[w][1][0], lane, force);
        __syncwarp();
        drift_stg(drift4 + base + F4T, &buf[w][1][0], lane);
    } else if (nfull == 1) {
        // ---- single full tile (R7-style), remainder scalar below ----
        uint32_t s0 = (uint32_t)__cvta_generic_to_shared(&buf[w][0][0]);
        #pragma unroll
        for (int k = 0; k < 5; k++)
            cp_async16(s0 + (uint32_t)(lane + k * 32) * 16u,
                       x4 + base + lane + k * 32);
        asm volatile("cp.async.commit_group;\n" ::: "memory");
        diffu_stg(diffu4 + base, lane);
        asm volatile("cp.async.wait_group 0;\n" ::: "memory");
        __syncwarp();
        compute_tile(&buf[w][0][0], lane, force);
        __syncwarp();
        drift_stg(drift4 + base, &buf[w][0][0], lane);
    }

    // ---- scalar remainder rows inside this warp's range ----
    int r0 = row_base + nfull * 128;
    int r1 = row_base + ROWS_PER_WARP; if (r1 > B) r1 = B;
    if (r0 < r1) {
        const float* xs = (const float*)x4;
        float* drs = (float*)drift4;
        float* dfs = (float*)diffu4;
        for (int r = r0 + lane; r < r1; r += 32) {
            const float* xr = xs + (size_t)r * 5;
            float o[5];
            hb_row(xr[0], xr[1], xr[2], xr[3], xr[4], force, o);
            float* dr = drs + (size_t)r * 5;
            float* gr = dfs + (size_t)r * 5;
            dr[0] = o[0]; dr[1] = o[1]; dr[2] = o[2]; dr[3] = o[3]; dr[4] = o[4];
            gr[0] = 0.05f; gr[1] = 0.02f; gr[2] = 0.0f; gr[3] = 0.0f; gr[4] = 0.0f;
        }
    }
}

extern "C" void kernel_launch(void* const* d_in, const int* in_sizes, int n_in,
                              void* d_out, int out_size) {
    const float* t  = (const float*)d_in[0];   // [1]
    const float* x  = (const float*)d_in[1];   // [B*5]
    float* out      = (float*)d_out;
    int B           = in_sizes[1] / 5;
    int nf4         = in_sizes[1] / 4;         // B*5 % 4 == 0 for B=8M
    float* drift    = out;
    float* diffu    = out + (size_t)out_size / 2;

    int nwarps  = (B + ROWS_PER_WARP - 1) / ROWS_PER_WARP;  // 31250 for B=8M
    int nblocks = (nwarps + WPB - 1) / WPB;                 // 3907

    hb_kernel<<<nblocks, TPB>>>(t, (const float4*)x,
                                (float4*)drift, (float4*)diffu, nf4, B);
}